// round 15
// baseline (speedup 1.0000x reference)
#include <cuda_runtime.h>
#include <math.h>

#define NB 16
#define NA 65536
#define NM 64
#define TPB 256
#define GRIDX 74                 // 16 * 74 = 1184 = 148 SMs x 8 blocks
#define NBLOCKS (NB * GRIDX)
#define BINW 64.0f
#define NBINS 160     // anchor centers in [0, 10000) -> bin <= 156
#define KCAP 6        // fixed per-bin slots (3 x float4); overflow -> full scan

__device__ float g_ls[NBLOCKS];
__device__ int   g_np[NBLOCKS];
__device__ int   g_count = 0;

// Tournament combine: take right if strictly better (cross-multiplied IoU
// compare, no division). Keep-left-on-tie + index-ordered pairing preserves
// the reference's first-maximum argmax semantics.
__device__ __forceinline__ void comb(float& iwl, float& sl, float& b0l, float& b1l,
                                     float iwr, float sr, float b0r, float b1r) {
    bool c = iwr * sl > iwl * sr;
    iwl = c ? iwr : iwl;
    sl  = c ? sr  : sl;
    b0l = c ? b0r : b0l;
    b1l = c ? b1r : b1l;
}

// Position of the (n+1)-th set bit of a 64-bit mask (n < popcll(m)).
__device__ __forceinline__ int nth_set_bit64(unsigned long long m, int n) {
    unsigned lo = (unsigned)m, hi = (unsigned)(m >> 32);
    int plo = __popc(lo);
    unsigned w = (n < plo) ? lo : hi;
    int base   = (n < plo) ? 0 : 32;
    int nn     = (n < plo) ? n : n - plo;
    return base + __fns(w, 0, nn + 1);
}

__global__ __launch_bounds__(TPB) void rl_kernel(
    const float* __restrict__ reg,      // (B, A, 2)
    const float* __restrict__ anchors,  // (1, A, 2)
    const float* __restrict__ ann,      // (B, M, 3)
    float* __restrict__ out)
{
    const int b   = blockIdx.y;
    const int tid = threadIdx.x;

    // Boxes as (b0, b1). Invalid/pad -> sentinel (3e18, -3e18): iw ~ -6e18,
    // s ~ -6e18; a real box beats a sentinel from either side of the
    // cross-mult compare, sentinels never win over real boxes, all products
    // stay finite. Empty bin -> sentinel winner -> pos test false.
    __shared__ float2 sbox[NM];
    __shared__ unsigned long long smask[NBINS];
    __shared__ float2 slist[NBINS * KCAP];   // 48B per bin, 16B-aligned groups
    __shared__ int    scnt[NBINS];

    // Region 1: load boxes (tid<64) in parallel with zeroing masks.
    if (tid < NM) {
        const float* a3 = ann + ((size_t)b * NM + tid) * 3;
        float b0 = a3[0], b1 = a3[1], lab = a3[2];
        bool valid = (lab != -1.0f);
        sbox[tid] = valid ? make_float2(b0, b1) : make_float2(3e18f, -3e18f);
    } else if (tid >= 64 && tid < 64 + NBINS) {
        smask[tid - 64] = 0ull;
    }
    __syncthreads();

    // Region 2: scatter — one thread per box marks the <=4 bins it can
    // influence. Bin j accepts anchors with center in [j*64,(j+1)*64);
    // anchor half-width <= 30, so a box overlaps such an anchor only if
    //   b1 > j*64 - 30  &&  b0 < j*64 + 94.
    if (tid < NM) {
        float2 bx = sbox[tid];
        if (bx.x < bx.y) {   // real box
            int jlo = (int)((bx.x - 94.0f) * (1.0f / BINW)) - 1;
            if (jlo < 0) jlo = 0;
            unsigned long long bit = 1ull << tid;
            for (int j = jlo; j < NBINS; j++) {
                float base = (float)j * BINW;
                if (base - 30.0f >= bx.y) break;
                if (bx.x < base + 94.0f)
                    atomicOr(&smask[j], bit);
            }
        }
    }
    __syncthreads();

    // Region 3: gather — fully parallel over (bin, slot) pairs. Ascending
    // bit position = ascending box index -> first-max argmax preserved.
    #pragma unroll
    for (int pair = tid; pair < NBINS * KCAP; pair += TPB) {
        int bin  = pair / KCAP;
        int slot = pair - bin * KCAP;
        unsigned long long m = smask[bin];
        int pc = __popcll(m);
        float2 v = make_float2(3e18f, -3e18f);
        if (slot < pc && slot < KCAP)
            v = sbox[nth_set_bit64(m, slot)];
        slist[pair] = v;
        if (slot == 0) scnt[bin] = pc;
    }
    __syncthreads();

    float lsum = 0.0f;
    int   lpos = 0;

    const float2* anc2 = (const float2*)anchors;
    const float2* reg2 = (const float2*)(reg + (size_t)b * NA * 2);
    const float4* sl4  = (const float4*)slist;
    const int abase  = blockIdx.x * TPB + tid;
    const int stride = GRIDX * TPB;     // 18944

    #pragma unroll 4
    for (int a = abase; a < NA; a += stride) {
        float2 av = anc2[a];
        float2 r  = reg2[a];          // unconditional: coalesced, MLP
        const float a0 = av.x, a1 = av.y;
        const float aw   = a1 - a0;
        const float actr = 0.5f * a0 + 0.5f * a1;

        const int bin = (int)(actr * (1.0f / BINW));   // 0..156
        const int cnt = scnt[bin];

        float iw0, s0, bb0, bb1;
        if (cnt <= KCAP) {
            // 3 independent LDS.128 -> 6 candidate boxes
            float4 q0 = sl4[bin * 3 + 0];
            float4 q1 = sl4[bin * 3 + 1];
            float4 q2 = sl4[bin * 3 + 2];

            float iwA = fminf(a1, q0.y) - fmaxf(a0, q0.x), sA = aw + (q0.y - q0.x);
            float iwB = fminf(a1, q0.w) - fmaxf(a0, q0.z), sB = aw + (q0.w - q0.z);
            float iwC = fminf(a1, q1.y) - fmaxf(a0, q1.x), sC = aw + (q1.y - q1.x);
            float iwD = fminf(a1, q1.w) - fmaxf(a0, q1.z), sD = aw + (q1.w - q1.z);
            float iwE = fminf(a1, q2.y) - fmaxf(a0, q2.x), sE = aw + (q2.y - q2.x);
            float iwF = fminf(a1, q2.w) - fmaxf(a0, q2.z), sF = aw + (q2.w - q2.z);

            // tournament: 3 independent combines, then 2 (depth 3)
            float b0A = q0.x, b1A = q0.y;
            float b0C = q1.x, b1C = q1.y;
            float b0E = q2.x, b1E = q2.y;
            comb(iwA, sA, b0A, b1A, iwB, sB, q0.z, q0.w);
            comb(iwC, sC, b0C, b1C, iwD, sD, q1.z, q1.w);
            comb(iwE, sE, b0E, b1E, iwF, sF, q2.z, q2.w);
            comb(iwA, sA, b0A, b1A, iwC, sC, b0C, b1C);
            comb(iwA, sA, b0A, b1A, iwE, sE, b0E, b1E);
            iw0 = iwA; s0 = sA; bb0 = b0A; bb1 = b1A;
        } else {  // overflow fallback (P ~ 1e-4 per bin): full scan, correct
            iw0 = 0.0f; s0 = 1.0f; bb0 = 0.0f; bb1 = 0.0f;
            #pragma unroll 8
            for (int k = 0; k < NM; k++) {
                float2 bx = sbox[k];
                float s  = aw + (bx.y - bx.x);
                float iw = fminf(a1, bx.y) - fmaxf(a0, bx.x);
                if (iw * s0 > iw0 * s) {
                    iw0 = iw; s0 = s; bb0 = bx.x; bb1 = bx.y;
                }
            }
        }

        // pos: iou >= 0.5  <=>  3*iw >= s  (exact under the 1e-8 clamp for
        // iw > 0; false for iw <= 0 and for sentinel winners)
        if (3.0f * iw0 >= s0) {
            lpos++;
            float gwr  = bb1 - bb0;
            float gctr = bb0 + 0.5f * gwr;
            float gw   = fmaxf(gwr, 1.0f);

            // fast-math: ~1e-7 rel err vs 1e-3 threshold (measured 0.0 R3-R14)
            float tdx = __fdividef(gctr - actr, aw) * 10.0f;
            float tdw = __logf(__fdividef(gw, aw)) * 5.0f;

            float d0 = fabsf(tdx - r.x);
            float d1 = fabsf(tdw - r.y);
            const float third = 1.0f / 9.0f;
            lsum += (d0 <= third) ? 4.5f * d0 * d0 : d0 - (0.5f / 9.0f);
            lsum += (d1 <= third) ? 4.5f * d1 * d1 : d1 - (0.5f / 9.0f);
        }
    }

    // Block reduction (8 warps)
    #pragma unroll
    for (int off = 16; off > 0; off >>= 1) {
        lsum += __shfl_down_sync(0xFFFFFFFFu, lsum, off);
        lpos += __shfl_down_sync(0xFFFFFFFFu, lpos, off);
    }
    __shared__ float wsum[TPB / 32];
    __shared__ int   wpos[TPB / 32];
    __shared__ int   slast;
    int wid = tid >> 5, lane = tid & 31;
    if (lane == 0) { wsum[wid] = lsum; wpos[wid] = lpos; }
    __syncthreads();

    if (tid == 0) {
        float s = 0.0f; int p = 0;
        #pragma unroll
        for (int i = 0; i < TPB / 32; i++) { s += wsum[i]; p += wpos[i]; }
        int slot = b * GRIDX + blockIdx.x;
        g_ls[slot] = s;
        g_np[slot] = p;
        __threadfence();
        int c = atomicAdd(&g_count, 1);
        slast = (c == NBLOCKS - 1) ? 1 : 0;
    }
    __syncthreads();
    if (!slast) return;

    // ---- Last block: reduce 1184 partials and write the scalar. ----
    if (tid == 0) g_count = 0;   // replay-safe reset

    int bb = tid >> 4;           // image 0..15
    int j  = tid & 15;
    float s = 0.0f; int p = 0;
    for (int idx = j; idx < GRIDX; idx += 16) {   // 74 partials per image
        s += __ldcg(&g_ls[bb * GRIDX + idx]);
        p += __ldcg(&g_np[bb * GRIDX + idx]);
    }
    #pragma unroll
    for (int off = 8; off > 0; off >>= 1) {
        s += __shfl_down_sync(0xFFFFFFFFu, s, off, 16);
        p += __shfl_down_sync(0xFFFFFFFFu, p, off, 16);
    }
    __shared__ float simg[NB];
    if (j == 0) {
        // npos > 0 implies a valid box exists, so valid.any() is subsumed.
        simg[bb] = (p > 0) ? s / (2.0f * (float)p) : 0.0f;
    }
    __syncthreads();
    if (tid < 32) {
        float l = (tid < NB) ? simg[tid] : 0.0f;
        #pragma unroll
        for (int off = 16; off > 0; off >>= 1)
            l += __shfl_down_sync(0xFFFFFFFFu, l, off);
        if (tid == 0) out[0] = l / (float)NB;
    }
}

extern "C" void kernel_launch(void* const* d_in, const int* in_sizes, int n_in,
                              void* d_out, int out_size) {
    const float* reg     = (const float*)d_in[0];  // (16, 65536, 2)
    const float* anchors = (const float*)d_in[1];  // (1, 65536, 2)
    const float* ann     = (const float*)d_in[2];  // (16, 64, 3)
    float* out = (float*)d_out;

    dim3 grid(GRIDX, NB);
    rl_kernel<<<grid, TPB>>>(reg, anchors, ann, out);
}

// round 16
// speedup vs baseline: 1.0014x; 1.0014x over previous
#include <cuda_runtime.h>
#include <math.h>

#define NB 16
#define NA 65536
#define NM 64
#define TPB 256
#define GRIDX 74                 // 16 * 74 = 1184 = 148 SMs x 8 blocks
#define NBLOCKS (NB * GRIDX)
#define BINW 64.0f
#define NBINS 160     // anchor centers in [0, 10000) -> bin <= 156
#define KCAP 6        // fixed per-bin slots (3 x float4); overflow -> full scan

__device__ float g_ls[NBLOCKS];
__device__ int   g_np[NBLOCKS];
__device__ int   g_count = 0;

// Tournament combine: take right if strictly better (cross-multiplied IoU
// compare, no division). Keep-left-on-tie + index-ordered pairing preserves
// the reference's first-maximum argmax semantics.
__device__ __forceinline__ void comb(float& iwl, float& sl, float& b0l, float& b1l,
                                     float iwr, float sr, float b0r, float b1r) {
    bool c = iwr * sl > iwl * sr;
    iwl = c ? iwr : iwl;
    sl  = c ? sr  : sl;
    b0l = c ? b0r : b0l;
    b1l = c ? b1r : b1l;
}

// Position of the (n+1)-th set bit of a 64-bit mask (n < popcll(m)).
__device__ __forceinline__ int nth_set_bit64(unsigned long long m, int n) {
    unsigned lo = (unsigned)m, hi = (unsigned)(m >> 32);
    int plo = __popc(lo);
    unsigned w = (n < plo) ? lo : hi;
    int base   = (n < plo) ? 0 : 32;
    int nn     = (n < plo) ? n : n - plo;
    return base + __fns(w, 0, nn + 1);
}

__global__ __launch_bounds__(TPB) void rl_kernel(
    const float* __restrict__ reg,      // (B, A, 2)
    const float* __restrict__ anchors,  // (1, A, 2)
    const float* __restrict__ ann,      // (B, M, 3)
    float* __restrict__ out)
{
    const int b   = blockIdx.y;
    const int tid = threadIdx.x;

    // Boxes as (b0, b1). Invalid/pad -> sentinel (3e18, -3e18): iw ~ -6e18,
    // s ~ -6e18; a real box beats a sentinel from either side of the
    // cross-mult compare, sentinels never win over real boxes, all products
    // stay finite. Empty bin -> sentinel winner -> pos test false.
    __shared__ float2 sbox[NM];
    __shared__ unsigned long long smask[NBINS];
    __shared__ float2 slist[NBINS * KCAP];   // 48B per bin, 16B-aligned groups
    __shared__ int    scnt[NBINS];

    // Region 1: load boxes (tid<64) in parallel with zeroing masks.
    if (tid < NM) {
        const float* a3 = ann + ((size_t)b * NM + tid) * 3;
        float b0 = a3[0], b1 = a3[1], lab = a3[2];
        bool valid = (lab != -1.0f);
        sbox[tid] = valid ? make_float2(b0, b1) : make_float2(3e18f, -3e18f);
    } else if (tid >= 64 && tid < 64 + NBINS) {
        smask[tid - 64] = 0ull;
    }
    __syncthreads();

    // Region 2: scatter — one thread per box marks the <=4 bins it can
    // influence. Bin j accepts anchors with center in [j*64,(j+1)*64);
    // anchor half-width <= 30, so a box overlaps such an anchor only if
    //   b1 > j*64 - 30  &&  b0 < j*64 + 94.
    if (tid < NM) {
        float2 bx = sbox[tid];
        if (bx.x < bx.y) {   // real box
            int jlo = (int)((bx.x - 94.0f) * (1.0f / BINW)) - 1;
            if (jlo < 0) jlo = 0;
            unsigned long long bit = 1ull << tid;
            for (int j = jlo; j < NBINS; j++) {
                float base = (float)j * BINW;
                if (base - 30.0f >= bx.y) break;
                if (bx.x < base + 94.0f)
                    atomicOr(&smask[j], bit);
            }
        }
    }
    __syncthreads();

    // Region 3: gather — fully parallel over (bin, slot) pairs. Ascending
    // bit position = ascending box index -> first-max argmax preserved.
    #pragma unroll
    for (int pair = tid; pair < NBINS * KCAP; pair += TPB) {
        int bin  = pair / KCAP;
        int slot = pair - bin * KCAP;
        unsigned long long m = smask[bin];
        int pc = __popcll(m);
        float2 v = make_float2(3e18f, -3e18f);
        if (slot < pc && slot < KCAP)
            v = sbox[nth_set_bit64(m, slot)];
        slist[pair] = v;
        if (slot == 0) scnt[bin] = pc;
    }
    __syncthreads();

    float lsum = 0.0f;
    int   lpos = 0;

    const float2* anc2 = (const float2*)anchors;
    const float2* reg2 = (const float2*)(reg + (size_t)b * NA * 2);
    const float4* sl4  = (const float4*)slist;
    const int abase  = blockIdx.x * TPB + tid;
    const int stride = GRIDX * TPB;     // 18944

    #pragma unroll 4
    for (int a = abase; a < NA; a += stride) {
        float2 av = anc2[a];
        float2 r  = reg2[a];          // unconditional: coalesced, MLP
        const float a0 = av.x, a1 = av.y;
        const float aw   = a1 - a0;
        const float actr = 0.5f * a0 + 0.5f * a1;

        const int bin = (int)(actr * (1.0f / BINW));   // 0..156
        const int cnt = scnt[bin];

        float iw0, s0, bb0, bb1;
        if (cnt <= KCAP) {
            // 3 independent LDS.128 -> 6 candidate boxes
            float4 q0 = sl4[bin * 3 + 0];
            float4 q1 = sl4[bin * 3 + 1];
            float4 q2 = sl4[bin * 3 + 2];

            float iwA = fminf(a1, q0.y) - fmaxf(a0, q0.x), sA = aw + (q0.y - q0.x);
            float iwB = fminf(a1, q0.w) - fmaxf(a0, q0.z), sB = aw + (q0.w - q0.z);
            float iwC = fminf(a1, q1.y) - fmaxf(a0, q1.x), sC = aw + (q1.y - q1.x);
            float iwD = fminf(a1, q1.w) - fmaxf(a0, q1.z), sD = aw + (q1.w - q1.z);
            float iwE = fminf(a1, q2.y) - fmaxf(a0, q2.x), sE = aw + (q2.y - q2.x);
            float iwF = fminf(a1, q2.w) - fmaxf(a0, q2.z), sF = aw + (q2.w - q2.z);

            // tournament: 3 independent combines, then 2 (depth 3)
            float b0A = q0.x, b1A = q0.y;
            float b0C = q1.x, b1C = q1.y;
            float b0E = q2.x, b1E = q2.y;
            comb(iwA, sA, b0A, b1A, iwB, sB, q0.z, q0.w);
            comb(iwC, sC, b0C, b1C, iwD, sD, q1.z, q1.w);
            comb(iwE, sE, b0E, b1E, iwF, sF, q2.z, q2.w);
            comb(iwA, sA, b0A, b1A, iwC, sC, b0C, b1C);
            comb(iwA, sA, b0A, b1A, iwE, sE, b0E, b1E);
            iw0 = iwA; s0 = sA; bb0 = b0A; bb1 = b1A;
        } else {  // overflow fallback (P ~ 1e-4 per bin): full scan, correct
            iw0 = 0.0f; s0 = 1.0f; bb0 = 0.0f; bb1 = 0.0f;
            #pragma unroll 8
            for (int k = 0; k < NM; k++) {
                float2 bx = sbox[k];
                float s  = aw + (bx.y - bx.x);
                float iw = fminf(a1, bx.y) - fmaxf(a0, bx.x);
                if (iw * s0 > iw0 * s) {
                    iw0 = iw; s0 = s; bb0 = bx.x; bb1 = bx.y;
                }
            }
        }

        // pos: iou >= 0.5  <=>  3*iw >= s  (exact under the 1e-8 clamp for
        // iw > 0; false for iw <= 0 and for sentinel winners)
        if (3.0f * iw0 >= s0) {
            lpos++;
            float gwr  = bb1 - bb0;
            float gctr = bb0 + 0.5f * gwr;
            float gw   = fmaxf(gwr, 1.0f);

            // fast-math: ~1e-7 rel err vs 1e-3 threshold (measured 0.0 R3-R14)
            float tdx = __fdividef(gctr - actr, aw) * 10.0f;
            float tdw = __logf(__fdividef(gw, aw)) * 5.0f;

            float d0 = fabsf(tdx - r.x);
            float d1 = fabsf(tdw - r.y);
            const float third = 1.0f / 9.0f;
            lsum += (d0 <= third) ? 4.5f * d0 * d0 : d0 - (0.5f / 9.0f);
            lsum += (d1 <= third) ? 4.5f * d1 * d1 : d1 - (0.5f / 9.0f);
        }
    }

    // Block reduction (8 warps)
    #pragma unroll
    for (int off = 16; off > 0; off >>= 1) {
        lsum += __shfl_down_sync(0xFFFFFFFFu, lsum, off);
        lpos += __shfl_down_sync(0xFFFFFFFFu, lpos, off);
    }
    __shared__ float wsum[TPB / 32];
    __shared__ int   wpos[TPB / 32];
    __shared__ int   slast;
    int wid = tid >> 5, lane = tid & 31;
    if (lane == 0) { wsum[wid] = lsum; wpos[wid] = lpos; }
    __syncthreads();

    if (tid == 0) {
        float s = 0.0f; int p = 0;
        #pragma unroll
        for (int i = 0; i < TPB / 32; i++) { s += wsum[i]; p += wpos[i]; }
        int slot = b * GRIDX + blockIdx.x;
        g_ls[slot] = s;
        g_np[slot] = p;
        __threadfence();
        int c = atomicAdd(&g_count, 1);
        slast = (c == NBLOCKS - 1) ? 1 : 0;
    }
    __syncthreads();
    if (!slast) return;

    // ---- Last block: reduce 1184 partials and write the scalar. ----
    if (tid == 0) g_count = 0;   // replay-safe reset

    int bb = tid >> 4;           // image 0..15
    int j  = tid & 15;
    float s = 0.0f; int p = 0;
    for (int idx = j; idx < GRIDX; idx += 16) {   // 74 partials per image
        s += __ldcg(&g_ls[bb * GRIDX + idx]);
        p += __ldcg(&g_np[bb * GRIDX + idx]);
    }
    #pragma unroll
    for (int off = 8; off > 0; off >>= 1) {
        s += __shfl_down_sync(0xFFFFFFFFu, s, off, 16);
        p += __shfl_down_sync(0xFFFFFFFFu, p, off, 16);
    }
    __shared__ float simg[NB];
    if (j == 0) {
        // npos > 0 implies a valid box exists, so valid.any() is subsumed.
        simg[bb] = (p > 0) ? s / (2.0f * (float)p) : 0.0f;
    }
    __syncthreads();
    if (tid < 32) {
        float l = (tid < NB) ? simg[tid] : 0.0f;
        #pragma unroll
        for (int off = 16; off > 0; off >>= 1)
            l += __shfl_down_sync(0xFFFFFFFFu, l, off);
        if (tid == 0) out[0] = l / (float)NB;
    }
}

extern "C" void kernel_launch(void* const* d_in, const int* in_sizes, int n_in,
                              void* d_out, int out_size) {
    const float* reg     = (const float*)d_in[0];  // (16, 65536, 2)
    const float* anchors = (const float*)d_in[1];  // (1, 65536, 2)
    const float* ann     = (const float*)d_in[2];  // (16, 64, 3)
    float* out = (float*)d_out;

    dim3 grid(GRIDX, NB);
    rl_kernel<<<grid, TPB>>>(reg, anchors, ann, out);
}

// round 17
// speedup vs baseline: 1.2162x; 1.2145x over previous
#include <cuda_runtime.h>
#include <math.h>

#define NB 16
#define NA 65536
#define NM 64
#define TPB 256
#define GRIDX 64
#define NBLOCKS (NB * GRIDX)
#define BINW 64.0f
#define NBINS 160     // anchor centers in [0, 10000) -> bin <= 156
#define KCAP 6        // fixed per-bin slots (overflow -> full-scan fallback)

__device__ float g_ls[NBLOCKS];
__device__ int   g_np[NBLOCKS];
__device__ int   g_count = 0;

__global__ __launch_bounds__(TPB) void rl_kernel(
    const float* __restrict__ reg,      // (B, A, 2)
    const float* __restrict__ anchors,  // (1, A, 2)
    const float* __restrict__ ann,      // (B, M, 3)
    float* __restrict__ out)
{
    const int b   = blockIdx.y;
    const int tid = threadIdx.x;

    // Boxes as (b0, b1); area recomputed as b1-b0. Invalid/pad -> sentinel
    // (3e18, -3e18): iw ~ -6e18 can never win the cross-mult compare because
    // best_s > best_iw >= 0 always holds (iou < 1), and products stay finite.
    __shared__ float2 sbox[NM];
    __shared__ float2 slist[NBINS * KCAP];
    __shared__ int    scnt[NBINS];

    if (tid < NM) {
        const float* a3 = ann + ((size_t)b * NM + tid) * 3;
        float b0 = a3[0], b1 = a3[1], lab = a3[2];
        if (lab == -1.0f) { b0 = 3e18f; b1 = -3e18f; }
        sbox[tid] = make_float2(b0, b1);
    }
    __syncthreads();

    // Bin j: anchors with center in [j*64, (j+1)*64); anchor half-width <= 30,
    // so any positively-overlapping box satisfies b1 > j*64-30 && b0 < j*64+94.
    // Lists built in ascending box index -> first-max argmax preserved.
    if (tid < NBINS) {
        float lo = (float)tid * BINW - 30.0f;
        float hi = (float)tid * BINW + (BINW + 30.0f);
        int c = 0;
        float2* lp = &slist[tid * KCAP];
        #pragma unroll
        for (int k = 0; k < NM; k++) {
            float2 bx = sbox[k];
            if (bx.y > lo && bx.x < hi) {
                if (c < KCAP) lp[c] = bx;
                c++;
            }
        }
        #pragma unroll
        for (int i = 0; i < KCAP; i++)
            if (i >= c) lp[i] = make_float2(3e18f, -3e18f);
        scnt[tid] = c;
    }
    __syncthreads();

    float lsum = 0.0f;
    int   lpos = 0;

    const float2* anc2 = (const float2*)anchors;
    const float2* reg2 = (const float2*)(reg + (size_t)b * NA * 2);
    const int abase = blockIdx.x * TPB + tid;

    #pragma unroll
    for (int j = 0; j < NA / (GRIDX * TPB); j++) {
        const int a = abase + j * (GRIDX * TPB);
        float2 av = anc2[a];
        const float a0 = av.x, a1 = av.y;
        const float aw   = a1 - a0;
        const float actr = a0 + 0.5f * aw;

        int bin = (int)(actr * (1.0f / BINW));
        int cnt = scnt[bin];

        // Cross-multiplied running argmax (no division):
        // iou_i > iou_j  <=>  iw_i * s_j > iw_j * s_i,  real s = aw+area > 0.
        // Init (0,1) = "iou 0"; strict '>' in ascending order = first max.
        float best_iw = 0.0f, best_s = 1.0f;
        float bb0 = 0.0f, bb1 = 0.0f;
        if (cnt <= KCAP) {
            const float2* lp = &slist[bin * KCAP];
            #pragma unroll
            for (int i = 0; i < KCAP; i++) {
                float2 bx = lp[i];
                float s  = aw + (bx.y - bx.x);
                float iw = fminf(a1, bx.y) - fmaxf(a0, bx.x);
                if (iw * best_s > best_iw * s) {
                    best_iw = iw; best_s = s; bb0 = bx.x; bb1 = bx.y;
                }
            }
        } else {  // overflow fallback (P ~ 1e-4 per bin): full scan, correct
            #pragma unroll 8
            for (int k = 0; k < NM; k++) {
                float2 bx = sbox[k];
                float s  = aw + (bx.y - bx.x);
                float iw = fminf(a1, bx.y) - fmaxf(a0, bx.x);
                if (iw * best_s > best_iw * s) {
                    best_iw = iw; best_s = s; bb0 = bx.x; bb1 = bx.y;
                }
            }
        }

        float ua = fmaxf(best_s - best_iw, 1e-8f);
        if (best_iw >= 0.5f * ua) {
            lpos++;
            float gwr  = bb1 - bb0;
            float gctr = bb0 + 0.5f * gwr;
            float gw   = fmaxf(gwr, 1.0f);

            // fast-math: ~1e-7 rel err vs 1e-3 threshold (measured 0.0)
            float tdx = __fdividef(gctr - actr, aw) * 10.0f;
            float tdw = __logf(__fdividef(gw, aw)) * 5.0f;

            float2 r = reg2[a];
            float d0 = fabsf(tdx - r.x);
            float d1 = fabsf(tdw - r.y);
            const float third = 1.0f / 9.0f;
            lsum += (d0 <= third) ? 4.5f * d0 * d0 : d0 - (0.5f / 9.0f);
            lsum += (d1 <= third) ? 4.5f * d1 * d1 : d1 - (0.5f / 9.0f);
        }
    }

    // Block reduction (8 warps)
    #pragma unroll
    for (int off = 16; off > 0; off >>= 1) {
        lsum += __shfl_down_sync(0xFFFFFFFFu, lsum, off);
        lpos += __shfl_down_sync(0xFFFFFFFFu, lpos, off);
    }
    __shared__ float wsum[TPB / 32];
    __shared__ int   wpos[TPB / 32];
    __shared__ int   slast;
    int wid = tid >> 5, lane = tid & 31;
    if (lane == 0) { wsum[wid] = lsum; wpos[wid] = lpos; }
    __syncthreads();

    if (tid == 0) {
        float s = 0.0f; int p = 0;
        #pragma unroll
        for (int i = 0; i < TPB / 32; i++) { s += wsum[i]; p += wpos[i]; }
        int slot = b * GRIDX + blockIdx.x;
        g_ls[slot] = s;
        g_np[slot] = p;
        __threadfence();
        int c = atomicAdd(&g_count, 1);
        slast = (c == NBLOCKS - 1) ? 1 : 0;
    }
    __syncthreads();
    if (!slast) return;

    // ---- Last block: reduce 1024 partials and write the scalar. ----
    if (tid == 0) g_count = 0;   // replay-safe reset

    int bb = tid >> 4;           // image 0..15
    int j  = tid & 15;
    float s = __ldcg(&g_ls[bb * GRIDX + j])
            + __ldcg(&g_ls[bb * GRIDX + j + 16])
            + __ldcg(&g_ls[bb * GRIDX + j + 32])
            + __ldcg(&g_ls[bb * GRIDX + j + 48]);
    int   p = __ldcg(&g_np[bb * GRIDX + j])
            + __ldcg(&g_np[bb * GRIDX + j + 16])
            + __ldcg(&g_np[bb * GRIDX + j + 32])
            + __ldcg(&g_np[bb * GRIDX + j + 48]);
    #pragma unroll
    for (int off = 8; off > 0; off >>= 1) {
        s += __shfl_down_sync(0xFFFFFFFFu, s, off, 16);
        p += __shfl_down_sync(0xFFFFFFFFu, p, off, 16);
    }
    __shared__ float simg[NB];
    if (j == 0) {
        // npos > 0 implies a valid box exists, so valid.any() is subsumed.
        simg[bb] = (p > 0) ? s / (2.0f * (float)p) : 0.0f;
    }
    __syncthreads();
    if (tid < 32) {
        float l = (tid < NB) ? simg[tid] : 0.0f;
        #pragma unroll
        for (int off = 16; off > 0; off >>= 1)
            l += __shfl_down_sync(0xFFFFFFFFu, l, off);
        if (tid == 0) out[0] = l / (float)NB;
    }
}

extern "C" void kernel_launch(void* const* d_in, const int* in_sizes, int n_in,
                              void* d_out, int out_size) {
    const float* reg     = (const float*)d_in[0];  // (16, 65536, 2)
    const float* anchors = (const float*)d_in[1];  // (1, 65536, 2)
    const float* ann     = (const float*)d_in[2];  // (16, 64, 3)
    float* out = (float*)d_out;

    dim3 grid(GRIDX, NB);
    rl_kernel<<<grid, TPB>>>(reg, anchors, ann, out);
}